// round 1
// baseline (speedup 1.0000x reference)
#include <cuda_runtime.h>
#include <math.h>

// ============================================================================
// HAN (2-layer heterogeneous GAT + semantic attention + MLP head), fp32.
//
// Inputs (metadata order):
//  0 x_object[No,128] 1 x_attribute[Na,128] 2 e_oo[2,E] 3 e_oa[2,E] 4 e_ao[2,E]
//  5..13  layer1: Wo,bo,Wa,ba,asrc[3,2,64],adst[3,2,64],Wk,bk,q
// 14..22  layer2: same
// 23..28  Wl1[128,256],bl1,Wl2[256,128],bl2,Wl3[128,8],bl3
// Output: sigmoid(res_obj @ Wl1 @ Wl2 @ Wl3) -> [No, 8] float
// ============================================================================

#define MAXNO 100096
#define MAXNA 50048
#define MAXE  500224

__device__ float  g_ho[MAXNO * 128];
__device__ float  g_ha[MAXNA * 128];
__device__ float  g_o0[MAXNO * 128];   // object output from oo metapath
__device__ float  g_o1[MAXNO * 128];   // object output from ao metapath
__device__ float  g_oa[MAXNA * 128];   // attribute output from oa metapath
__device__ float  g_res[MAXNO * 128];  // semantic-combined object features
__device__ float  g_x1[MAXNO * 256];   // MLP hidden
__device__ float  g_elog[MAXE * 2];    // per-edge per-head logits / exp values
__device__ float  g_m[MAXNO * 2];      // segment max
__device__ float  g_s[MAXNO * 2];      // segment sum
__device__ float  g_pobj[4 * MAXNO * 2]; // object node projections (4 vectors x H=2)
__device__ float  g_patt[2 * MAXNA * 2]; // attribute node projections
__device__ double g_score[2];
__device__ float  g_w[2];

// ---------------------------------------------------------------------------
// GEMM: C[M,N] = op(A)[M,K] @ W[K,N] + bias, op = optional relu, out optional sigmoid
// BM=128, BN=64, BK=16, 256 threads, 8x4 per-thread tile.
// Requires K % 16 == 0, N % 4 == 0.
// ---------------------------------------------------------------------------
#define GBM 128
#define GBN 64
#define GBK 16

__global__ __launch_bounds__(256) void gemm_bias_kernel(
    const float* __restrict__ A, const float* __restrict__ W,
    const float* __restrict__ bias, float* __restrict__ C,
    int M, int N, int K, int reluIn, int sigmoidOut)
{
    __shared__ float As[GBK][GBM];
    __shared__ float Bs[GBK][GBN];
    const int m0  = blockIdx.y * GBM;
    const int n0  = blockIdx.x * GBN;
    const int tid = threadIdx.x;
    const int ty  = tid >> 4;   // 0..15
    const int tx  = tid & 15;   // 0..15

    float acc[8][4];
#pragma unroll
    for (int i = 0; i < 8; i++)
#pragma unroll
        for (int j = 0; j < 4; j++) acc[i][j] = 0.f;

    for (int k0 = 0; k0 < K; k0 += GBK) {
        // load A tile: 128 rows x 16 cols
#pragma unroll
        for (int it = 0; it < 2; it++) {
            int lin = tid + it * 256;        // 0..511
            int m   = lin >> 2;              // 0..127
            int kv  = (lin & 3) << 2;        // 0,4,8,12
            float4 v = make_float4(0.f, 0.f, 0.f, 0.f);
            if (m0 + m < M)
                v = *(const float4*)(A + (size_t)(m0 + m) * K + (k0 + kv));
            if (reluIn) {
                v.x = fmaxf(v.x, 0.f); v.y = fmaxf(v.y, 0.f);
                v.z = fmaxf(v.z, 0.f); v.w = fmaxf(v.w, 0.f);
            }
            As[kv + 0][m] = v.x; As[kv + 1][m] = v.y;
            As[kv + 2][m] = v.z; As[kv + 3][m] = v.w;
        }
        // load W tile: 16 rows x 64 cols
        {
            int k  = tid >> 4;
            int nv = (tid & 15) << 2;
            float4 v = make_float4(0.f, 0.f, 0.f, 0.f);
            if (n0 + nv + 3 < N)
                v = *(const float4*)(W + (size_t)(k0 + k) * N + (n0 + nv));
            Bs[k][nv + 0] = v.x; Bs[k][nv + 1] = v.y;
            Bs[k][nv + 2] = v.z; Bs[k][nv + 3] = v.w;
        }
        __syncthreads();
#pragma unroll
        for (int k = 0; k < GBK; k++) {
            float4 a0 = *(const float4*)&As[k][ty * 8];
            float4 a1 = *(const float4*)&As[k][ty * 8 + 4];
            float4 b  = *(const float4*)&Bs[k][tx * 4];
            float a[8] = {a0.x, a0.y, a0.z, a0.w, a1.x, a1.y, a1.z, a1.w};
            float bb[4] = {b.x, b.y, b.z, b.w};
#pragma unroll
            for (int i = 0; i < 8; i++)
#pragma unroll
                for (int j = 0; j < 4; j++)
                    acc[i][j] += a[i] * bb[j];
        }
        __syncthreads();
    }
#pragma unroll
    for (int i = 0; i < 8; i++) {
        int m = m0 + ty * 8 + i;
        if (m >= M) continue;
#pragma unroll
        for (int j = 0; j < 4; j++) {
            int n = n0 + tx * 4 + j;
            if (n >= N) continue;
            float v = acc[i][j] + bias[n];
            if (sigmoidOut) v = 1.f / (1.f + expf(-v));
            C[(size_t)m * N + n] = v;
        }
    }
}

// ---------------------------------------------------------------------------
// Semantic score GEMM: accumulates sum_{n,c} q[c]*tanh((relu(A)@Wk + bk)[n,c])
// into outScore (double). Same tiling as gemm_bias_kernel, N=128, K=128.
// ---------------------------------------------------------------------------
__global__ __launch_bounds__(256) void score_gemm_kernel(
    const float* __restrict__ A, const float* __restrict__ W,
    const float* __restrict__ bias, const float* __restrict__ q,
    int M, int N, int K, double* __restrict__ outScore)
{
    __shared__ float As[GBK][GBM];
    __shared__ float Bs[GBK][GBN];
    const int m0  = blockIdx.y * GBM;
    const int n0  = blockIdx.x * GBN;
    const int tid = threadIdx.x;
    const int ty  = tid >> 4;
    const int tx  = tid & 15;

    float acc[8][4];
#pragma unroll
    for (int i = 0; i < 8; i++)
#pragma unroll
        for (int j = 0; j < 4; j++) acc[i][j] = 0.f;

    for (int k0 = 0; k0 < K; k0 += GBK) {
#pragma unroll
        for (int it = 0; it < 2; it++) {
            int lin = tid + it * 256;
            int m   = lin >> 2;
            int kv  = (lin & 3) << 2;
            float4 v = make_float4(0.f, 0.f, 0.f, 0.f);
            if (m0 + m < M)
                v = *(const float4*)(A + (size_t)(m0 + m) * K + (k0 + kv));
            // relu on input (metapath outputs pass through relu before stacking)
            v.x = fmaxf(v.x, 0.f); v.y = fmaxf(v.y, 0.f);
            v.z = fmaxf(v.z, 0.f); v.w = fmaxf(v.w, 0.f);
            As[kv + 0][m] = v.x; As[kv + 1][m] = v.y;
            As[kv + 2][m] = v.z; As[kv + 3][m] = v.w;
        }
        {
            int k  = tid >> 4;
            int nv = (tid & 15) << 2;
            float4 v = make_float4(0.f, 0.f, 0.f, 0.f);
            if (n0 + nv + 3 < N)
                v = *(const float4*)(W + (size_t)(k0 + k) * N + (n0 + nv));
            Bs[k][nv + 0] = v.x; Bs[k][nv + 1] = v.y;
            Bs[k][nv + 2] = v.z; Bs[k][nv + 3] = v.w;
        }
        __syncthreads();
#pragma unroll
        for (int k = 0; k < GBK; k++) {
            float4 a0 = *(const float4*)&As[k][ty * 8];
            float4 a1 = *(const float4*)&As[k][ty * 8 + 4];
            float4 b  = *(const float4*)&Bs[k][tx * 4];
            float a[8] = {a0.x, a0.y, a0.z, a0.w, a1.x, a1.y, a1.z, a1.w};
            float bb[4] = {b.x, b.y, b.z, b.w};
#pragma unroll
            for (int i = 0; i < 8; i++)
#pragma unroll
                for (int j = 0; j < 4; j++)
                    acc[i][j] += a[i] * bb[j];
        }
        __syncthreads();
    }
    float local = 0.f;
#pragma unroll
    for (int i = 0; i < 8; i++) {
        int m = m0 + ty * 8 + i;
        if (m >= M) continue;
#pragma unroll
        for (int j = 0; j < 4; j++) {
            int n = n0 + tx * 4 + j;
            if (n >= N) continue;
            local += q[n] * tanhf(acc[i][j] + bias[n]);
        }
    }
    __shared__ float red[256];
    red[tid] = local;
    __syncthreads();
#pragma unroll
    for (int s2 = 128; s2 > 0; s2 >>= 1) {
        if (tid < s2) red[tid] += red[tid + s2];
        __syncthreads();
    }
    if (tid == 0) atomicAdd(outScore, (double)red[0]);
}

// ---------------------------------------------------------------------------
// Node projection: out[v][node][h] = sum_d h[node, h, d] * vec_v[h, d]
// One warp per node. nv <= 4 vectors of 128 floats.
// ---------------------------------------------------------------------------
__global__ __launch_bounds__(256) void proj_kernel(
    const float* __restrict__ h, int n, int nv,
    const float* __restrict__ v0, const float* __restrict__ v1,
    const float* __restrict__ v2, const float* __restrict__ v3,
    float* __restrict__ out)
{
    int warp = (blockIdx.x * blockDim.x + threadIdx.x) >> 5;
    int lane = threadIdx.x & 31;
    if (warp >= n) return;
    const float* hr = h + (size_t)warp * 128;
    float h0 = hr[lane], h1 = hr[lane + 32], h2 = hr[lane + 64], h3 = hr[lane + 96];
    const float* vs[4] = {v0, v1, v2, v3};
#pragma unroll
    for (int v = 0; v < 4; v++) {
        if (v >= nv) break;
        const float* vv = vs[v];
        float p0 = h0 * vv[lane] + h1 * vv[lane + 32];         // head 0
        float p1 = h2 * vv[lane + 64] + h3 * vv[lane + 96];    // head 1
#pragma unroll
        for (int o = 16; o > 0; o >>= 1) {
            p0 += __shfl_xor_sync(0xffffffffu, p0, o);
            p1 += __shfl_xor_sync(0xffffffffu, p1, o);
        }
        if (lane == 0) {
            out[((size_t)v * n + warp) * 2 + 0] = p0;
            out[((size_t)v * n + warp) * 2 + 1] = p1;
        }
    }
}

// ---------------------------------------------------------------------------
// Edge-type init: zero the output accumulator [ndst,128], m=-inf, s=0
// ---------------------------------------------------------------------------
__global__ void init_seg_kernel(float* __restrict__ out, float* __restrict__ m,
                                float* __restrict__ s, int ndst)
{
    int i = blockIdx.x * blockDim.x + threadIdx.x;
    if (i < ndst * 128) out[i] = 0.f;
    if (i < ndst * 2) { m[i] = -INFINITY; s[i] = 0.f; }
}

__device__ __forceinline__ void atomicMaxFloat(float* addr, float val)
{
    if (val >= 0.f) atomicMax((int*)addr, __float_as_int(val));
    else            atomicMin((unsigned int*)addr, __float_as_uint(val));
}

// pass1: logits + leaky_relu, store, segment max
__global__ __launch_bounds__(256) void edge_logits_kernel(
    const int* __restrict__ src, const int* __restrict__ dst, int E,
    const float* __restrict__ psrc, const float* __restrict__ pdst,
    float* __restrict__ elog, float* __restrict__ m)
{
    int e = blockIdx.x * blockDim.x + threadIdx.x;
    if (e >= E) return;
    int s = src[e], d = dst[e];
    float2 ps = *(const float2*)(psrc + 2 * (size_t)s);
    float2 pd = *(const float2*)(pdst + 2 * (size_t)d);
    float a0 = ps.x + pd.x; a0 = a0 > 0.f ? a0 : 0.2f * a0;
    float a1 = ps.y + pd.y; a1 = a1 > 0.f ? a1 : 0.2f * a1;
    *(float2*)(elog + 2 * (size_t)e) = make_float2(a0, a1);
    atomicMaxFloat(m + 2 * (size_t)d + 0, a0);
    atomicMaxFloat(m + 2 * (size_t)d + 1, a1);
}

// pass2: e = exp(a - m[dst]), store, segment sum
__global__ __launch_bounds__(256) void edge_exp_kernel(
    const int* __restrict__ dst, int E, const float* __restrict__ m,
    float* __restrict__ elog, float* __restrict__ ssum)
{
    int e = blockIdx.x * blockDim.x + threadIdx.x;
    if (e >= E) return;
    int d = dst[e];
    float2 mv = *(const float2*)(m + 2 * (size_t)d);
    float2 ev = *(const float2*)(elog + 2 * (size_t)e);
    ev.x = expf(ev.x - mv.x);
    ev.y = expf(ev.y - mv.y);
    *(float2*)(elog + 2 * (size_t)e) = ev;
    atomicAdd(ssum + 2 * (size_t)d + 0, ev.x);
    atomicAdd(ssum + 2 * (size_t)d + 1, ev.y);
}

// pass3: out[dst] += h_src[src] * alpha  (warp per edge, float4 per lane,
// vectorized global reduction)
__global__ __launch_bounds__(256) void edge_aggregate_kernel(
    const int* __restrict__ src, const int* __restrict__ dst, int E,
    const float* __restrict__ elog, const float* __restrict__ ssum,
    const float* __restrict__ hsrc, float* __restrict__ out)
{
    int gw   = (blockIdx.x * blockDim.x + threadIdx.x) >> 5;
    int lane = threadIdx.x & 31;
    if (gw >= E) return;
    int s = src[gw], d = dst[gw];
    int head = lane >> 4;   // lanes 0-15 -> head0 (c 0..63), 16-31 -> head1
    float el = elog[2 * (size_t)gw + head];
    float sv = ssum[2 * (size_t)d + head];
    float alpha = el / (sv + 1e-16f);
    float4 v = *(const float4*)(hsrc + (size_t)s * 128 + lane * 4);
    v.x *= alpha; v.y *= alpha; v.z *= alpha; v.w *= alpha;
    float* op = out + (size_t)d * 128 + lane * 4;
    asm volatile("red.global.add.v4.f32 [%0], {%1,%2,%3,%4};"
                 :: "l"(op), "f"(v.x), "f"(v.y), "f"(v.z), "f"(v.w)
                 : "memory");
}

// ---------------------------------------------------------------------------
// Semantic attention tail
// ---------------------------------------------------------------------------
__global__ void zero_score_kernel(double* sc) { sc[0] = 0.0; sc[1] = 0.0; }

__global__ void softmax2_kernel(const double* __restrict__ sc,
                                float* __restrict__ w, double invN)
{
    double s0 = sc[0] * invN, s1 = sc[1] * invN;
    double mx = s0 > s1 ? s0 : s1;
    double e0 = exp(s0 - mx), e1 = exp(s1 - mx);
    double sum = e0 + e1;
    w[0] = (float)(e0 / sum);
    w[1] = (float)(e1 / sum);
}

__global__ __launch_bounds__(256) void combine_kernel(
    const float* __restrict__ o0, const float* __restrict__ o1,
    const float* __restrict__ w, float* __restrict__ res, int tot)
{
    int i = blockIdx.x * blockDim.x + threadIdx.x;
    if (i >= tot) return;
    res[i] = w[0] * fmaxf(o0[i], 0.f) + w[1] * fmaxf(o1[i], 0.f);
}

// ---------------------------------------------------------------------------
// Host orchestration
// ---------------------------------------------------------------------------
static inline int ceil_div(int a, int b) { return (a + b - 1) / b; }

extern "C" void kernel_launch(void* const* d_in, const int* in_sizes, int n_in,
                              void* d_out, int out_size)
{
    const float* xo  = (const float*)d_in[0];
    const float* xa  = (const float*)d_in[1];
    const int*   eoo = (const int*)d_in[2];
    const int*   eoa = (const int*)d_in[3];
    const int*   eao = (const int*)d_in[4];
    const int No  = in_sizes[0] / 128;
    const int Na  = in_sizes[1] / 128;
    const int Eoo = in_sizes[2] / 2;
    const int Eoa = in_sizes[3] / 2;
    const int Eao = in_sizes[4] / 2;

    float *ho, *ha, *o0, *o1, *oa, *res, *x1, *elog, *m, *s, *pobj, *patt, *w;
    double* score;
    cudaGetSymbolAddress((void**)&ho,    g_ho);
    cudaGetSymbolAddress((void**)&ha,    g_ha);
    cudaGetSymbolAddress((void**)&o0,    g_o0);
    cudaGetSymbolAddress((void**)&o1,    g_o1);
    cudaGetSymbolAddress((void**)&oa,    g_oa);
    cudaGetSymbolAddress((void**)&res,   g_res);
    cudaGetSymbolAddress((void**)&x1,    g_x1);
    cudaGetSymbolAddress((void**)&elog,  g_elog);
    cudaGetSymbolAddress((void**)&m,     g_m);
    cudaGetSymbolAddress((void**)&s,     g_s);
    cudaGetSymbolAddress((void**)&pobj,  g_pobj);
    cudaGetSymbolAddress((void**)&patt,  g_patt);
    cudaGetSymbolAddress((void**)&score, g_score);
    cudaGetSymbolAddress((void**)&w,     g_w);

    dim3 gemmBlk(256);

    for (int layer = 0; layer < 2; layer++) {
        const int base = 5 + 9 * layer;
        const float* Wo   = (const float*)d_in[base + 0];
        const float* bo   = (const float*)d_in[base + 1];
        const float* Wa   = (const float*)d_in[base + 2];
        const float* ba   = (const float*)d_in[base + 3];
        const float* asrc = (const float*)d_in[base + 4];  // [3][128]
        const float* adst = (const float*)d_in[base + 5];  // [3][128]
        const float* Wk   = (const float*)d_in[base + 6];
        const float* bk   = (const float*)d_in[base + 7];
        const float* q    = (const float*)d_in[base + 8];

        const float* Ain_o = (layer == 0) ? xo : res;
        const float* Ain_a = (layer == 0) ? xa : oa;   // layer2 attr input = relu(oa_L1)
        int reluA = (layer == 0) ? 0 : 1;

        // feature transforms
        gemm_bias_kernel<<<dim3(ceil_div(128, GBN), ceil_div(No, GBM)), gemmBlk>>>(
            Ain_o, Wo, bo, ho, No, 128, 128, 0, 0);
        gemm_bias_kernel<<<dim3(ceil_div(128, GBN), ceil_div(Na, GBM)), gemmBlk>>>(
            Ain_a, Wa, ba, ha, Na, 128, 128, reluA, 0);

        // node projections: obj vectors {asrc0, asrc1, adst0, adst2}, attr {asrc2, adst1}
        proj_kernel<<<ceil_div(No * 32, 256), 256>>>(
            ho, No, 4, asrc + 0, asrc + 128, adst + 0, adst + 256, pobj);
        proj_kernel<<<ceil_div(Na * 32, 256), 256>>>(
            ha, Na, 2, asrc + 256, adst + 128, asrc, asrc, patt);

        // --- edge type oo: object -> object, metapath 0 ---
        {
            const int* esrc = eoo; const int* edst = eoo + Eoo;
            init_seg_kernel<<<ceil_div(No * 128, 256), 256>>>(o0, m, s, No);
            edge_logits_kernel<<<ceil_div(Eoo, 256), 256>>>(
                esrc, edst, Eoo, pobj + 0, pobj + (size_t)2 * No * 2, elog, m);
            edge_exp_kernel<<<ceil_div(Eoo, 256), 256>>>(edst, Eoo, m, elog, s);
            edge_aggregate_kernel<<<ceil_div(Eoo * 32, 256), 256>>>(
                esrc, edst, Eoo, elog, s, ho, o0);
        }
        // --- edge type oa: object -> attribute (only layer 1's result is used) ---
        if (layer == 0) {
            const int* esrc = eoa; const int* edst = eoa + Eoa;
            init_seg_kernel<<<ceil_div(Na * 128, 256), 256>>>(oa, m, s, Na);
            edge_logits_kernel<<<ceil_div(Eoa, 256), 256>>>(
                esrc, edst, Eoa, pobj + (size_t)1 * No * 2, patt + (size_t)1 * Na * 2, elog, m);
            edge_exp_kernel<<<ceil_div(Eoa, 256), 256>>>(edst, Eoa, m, elog, s);
            edge_aggregate_kernel<<<ceil_div(Eoa * 32, 256), 256>>>(
                esrc, edst, Eoa, elog, s, ho, oa);
        }
        // --- edge type ao: attribute -> object, metapath 1 ---
        {
            const int* esrc = eao; const int* edst = eao + Eao;
            init_seg_kernel<<<ceil_div(No * 128, 256), 256>>>(o1, m, s, No);
            edge_logits_kernel<<<ceil_div(Eao, 256), 256>>>(
                esrc, edst, Eao, patt + 0, pobj + (size_t)3 * No * 2, elog, m);
            edge_exp_kernel<<<ceil_div(Eao, 256), 256>>>(edst, Eao, m, elog, s);
            edge_aggregate_kernel<<<ceil_div(Eao * 32, 256), 256>>>(
                esrc, edst, Eao, elog, s, ha, o1);
        }

        // semantic attention over {oo, ao} for object nodes
        zero_score_kernel<<<1, 1>>>(score);
        score_gemm_kernel<<<dim3(ceil_div(128, GBN), ceil_div(No, GBM)), gemmBlk>>>(
            o0, Wk, bk, q, No, 128, 128, score + 0);
        score_gemm_kernel<<<dim3(ceil_div(128, GBN), ceil_div(No, GBM)), gemmBlk>>>(
            o1, Wk, bk, q, No, 128, 128, score + 1);
        softmax2_kernel<<<1, 1>>>(score, w, 1.0 / (double)No);
        combine_kernel<<<ceil_div(No * 128, 256), 256>>>(o0, o1, w, res, No * 128);
        // attribute result (M=1 metapath): res_attr = relu(oa), applied lazily at
        // layer-2 GEMM input (reluA=1).
    }

    // final MLP: 128 -> 256 -> 128 -> 8, sigmoid
    const float* Wl1 = (const float*)d_in[23];
    const float* bl1 = (const float*)d_in[24];
    const float* Wl2 = (const float*)d_in[25];
    const float* bl2 = (const float*)d_in[26];
    const float* Wl3 = (const float*)d_in[27];
    const float* bl3 = (const float*)d_in[28];

    gemm_bias_kernel<<<dim3(ceil_div(256, GBN), ceil_div(No, GBM)), gemmBlk>>>(
        res, Wl1, bl1, x1, No, 256, 128, 0, 0);
    gemm_bias_kernel<<<dim3(ceil_div(128, GBN), ceil_div(No, GBM)), gemmBlk>>>(
        x1, Wl2, bl2, ho, No, 128, 256, 0, 0);   // reuse g_ho as scratch
    gemm_bias_kernel<<<dim3(ceil_div(8, GBN), ceil_div(No, GBM)), gemmBlk>>>(
        ho, Wl3, bl3, (float*)d_out, No, 8, 128, 0, 1);
}